// round 7
// baseline (speedup 1.0000x reference)
#include <cuda_runtime.h>
#include <cuda_bf16.h>
#include <cstdint>
#include <math.h>

// ---- arch-feature gate: tcgen05 only exists in sm_103a/sm_100a passes ----
#if defined(__CUDA_ARCH_FEAT_SM103_ALL) || defined(__CUDA_ARCH_FEAT_SM100_ALL) || defined(__CUDA_ARCH_FEAT_SM101_ALL)
#define HAS_TC 1
#else
#define HAS_TC 0
#endif

// ---------------- problem constants ----------------
static constexpr int B_   = 8;
static constexpr int T_   = 2048;
static constexpr int C_   = 1024;
static constexpr int E_   = 8;
static constexpr int H_   = 4096;
static constexpr int N_   = B_ * T_;        // 16384 tokens
static constexpr int CAP_ = 4096;

// ---------------- device scratch (static, allocation-free) ----------------
__device__ __nv_bfloat16 g_x_hi[(size_t)N_ * C_];
__device__ __nv_bfloat16 g_x_lo[(size_t)N_ * C_];
__device__ __nv_bfloat16 g_w1t_hi[(size_t)E_ * H_ * C_];   // [e][h][c]
__device__ __nv_bfloat16 g_w1t_lo[(size_t)E_ * H_ * C_];
__device__ __nv_bfloat16 g_w2t_hi[(size_t)E_ * C_ * H_];   // [e][c][h]
__device__ __nv_bfloat16 g_w2t_lo[(size_t)E_ * C_ * H_];
__device__ __nv_bfloat16 g_h_hi[(size_t)E_ * CAP_ * H_];
__device__ __nv_bfloat16 g_h_lo[(size_t)E_ * CAP_ * H_];
__device__ float         g_h_f32[(size_t)E_ * CAP_ * H_];  // SIMT fallback path

__device__ float         g_gates[(size_t)N_ * E_];
__device__ unsigned char g_mask[N_];
__device__ int           g_dispatch[E_ * CAP_];
__device__ float         g_gslot[E_ * CAP_];
__device__ int           g_count[E_];
__device__ double        g_gatesum[E_];
__device__ int           g_use_simt;       // runtime dispatch flag (set by check_h)

// ---------------- PTX helpers ----------------
__device__ __forceinline__ uint32_t elect_one_pred() {
    uint32_t pred;
    asm volatile(
        "{\n\t.reg .pred p;\n\t"
        "elect.sync _|p, 0xFFFFFFFF;\n\t"
        "selp.b32 %0, 1, 0, p;\n\t}"
        : "=r"(pred));
    return pred;
}
__device__ __forceinline__ uint32_t smem_u32(const void* p) {
    uint32_t a;
    asm("{ .reg .u64 t; cvta.to.shared.u64 t, %1; cvt.u32.u64 %0, t; }" : "=r"(a) : "l"(p));
    return a;
}
__device__ __forceinline__ uint32_t swz(uint32_t off) { return off ^ ((off >> 3) & 0x70u); }

static constexpr uint64_t SMEM_DESC_BASE_SW128 =
    (uint64_t(2) << 61) | (uint64_t(1) << 46) | (uint64_t(64) << 32) | (uint64_t(1) << 16);
__device__ __forceinline__ uint64_t make_desc(uint32_t addr) {
    return SMEM_DESC_BASE_SW128 | ((uint64_t)(addr >> 4) & 0x3FFF);
}

#if HAS_TC
#define TCG_ALLOC(smem_addr, n) \
    asm volatile("tcgen05.alloc.cta_group::1.sync.aligned.shared::cta.b32 [%0], %1;" \
                 :: "r"((uint32_t)(smem_addr)), "r"((uint32_t)(n)) : "memory")
#define TCG_DEALLOC(tmem, n) \
    asm volatile("tcgen05.dealloc.cta_group::1.sync.aligned.b32 %0, %1;" :: "r"(tmem), "r"((uint32_t)(n)))
#define TCG_RELINQ() asm volatile("tcgen05.relinquish_alloc_permit.cta_group::1.sync.aligned;")
#define TCG_COMMIT(mbar) \
    asm volatile("tcgen05.commit.cta_group::1.mbarrier::arrive::one.shared::cluster.b64 [%0];" \
                 :: "r"((uint32_t)(mbar)) : "memory")
#define TCG_FENCE_AFTER()  asm volatile("tcgen05.fence::after_thread_sync;" ::: "memory")
#define TCG_FENCE_BEFORE() asm volatile("tcgen05.fence::before_thread_sync;" ::: "memory")
#define TCG_WAIT_LD()      asm volatile("tcgen05.wait::ld.sync.aligned;" ::: "memory")
#define TCG_WAIT_ST()      asm volatile("tcgen05.wait::st.sync.aligned;" ::: "memory")
#endif

#define MBAR_INIT(a, c) \
    asm volatile("mbarrier.init.shared.b64 [%0], %1;" :: "r"((uint32_t)(a)), "r"((uint32_t)(c)) : "memory")
#define FENCE_ASYNC() asm volatile("fence.proxy.async.shared::cta;" ::: "memory")

__device__ __forceinline__ void mbar_wait(uint32_t mbar, uint32_t parity) {
    asm volatile(
        "{\n\t.reg .pred P;\n\t"
        "WL%=:\n\t"
        "mbarrier.try_wait.parity.acquire.cta.shared::cta.b64 P, [%0], %1, 0x989680;\n\t"
        "@P bra WD%=;\n\t"
        "bra WL%=;\n\t"
        "WD%=:\n\t}"
        :: "r"(mbar), "r"(parity) : "memory");
}

#if HAS_TC
// TS-mode f16 MMA (A in TMEM, B via smem descriptor) — form verbatim from TCGEN05_MMA_F16
__device__ __forceinline__ void mma_f16_ts(uint32_t d, uint32_t a_tmem, uint64_t b_desc,
                                           uint32_t idesc, uint32_t en) {
    asm volatile(
        "{\n\t.reg .pred p;\n\t"
        "setp.ne.u32 p, %5, 0;\n\t"
        "tcgen05.mma.cta_group::1.kind::f16 [%0], [%1], %2, %3, {%4, %4, %4, %4}, p;\n\t}"
        :: "r"(d), "r"(a_tmem), "l"(b_desc), "r"(idesc), "r"(0u), "r"(en) : "memory");
}

#define TCG_ST_X64(tmem_addr, r) \
    asm volatile( \
        "tcgen05.st.sync.aligned.32x32b.x64.b32 [%0], " \
        "{%1, %2, %3, %4, %5, %6, %7, %8, " \
        " %9, %10, %11, %12, %13, %14, %15, %16, " \
        " %17, %18, %19, %20, %21, %22, %23, %24, " \
        " %25, %26, %27, %28, %29, %30, %31, %32, " \
        " %33, %34, %35, %36, %37, %38, %39, %40, " \
        " %41, %42, %43, %44, %45, %46, %47, %48, " \
        " %49, %50, %51, %52, %53, %54, %55, %56, " \
        " %57, %58, %59, %60, %61, %62, %63, %64};" \
        :: "r"(tmem_addr), \
           "r"((r)[0]),  "r"((r)[1]),  "r"((r)[2]),  "r"((r)[3]), \
           "r"((r)[4]),  "r"((r)[5]),  "r"((r)[6]),  "r"((r)[7]), \
           "r"((r)[8]),  "r"((r)[9]),  "r"((r)[10]), "r"((r)[11]), \
           "r"((r)[12]), "r"((r)[13]), "r"((r)[14]), "r"((r)[15]), \
           "r"((r)[16]), "r"((r)[17]), "r"((r)[18]), "r"((r)[19]), \
           "r"((r)[20]), "r"((r)[21]), "r"((r)[22]), "r"((r)[23]), \
           "r"((r)[24]), "r"((r)[25]), "r"((r)[26]), "r"((r)[27]), \
           "r"((r)[28]), "r"((r)[29]), "r"((r)[30]), "r"((r)[31]), \
           "r"((r)[32]), "r"((r)[33]), "r"((r)[34]), "r"((r)[35]), \
           "r"((r)[36]), "r"((r)[37]), "r"((r)[38]), "r"((r)[39]), \
           "r"((r)[40]), "r"((r)[41]), "r"((r)[42]), "r"((r)[43]), \
           "r"((r)[44]), "r"((r)[45]), "r"((r)[46]), "r"((r)[47]), \
           "r"((r)[48]), "r"((r)[49]), "r"((r)[50]), "r"((r)[51]), \
           "r"((r)[52]), "r"((r)[53]), "r"((r)[54]), "r"((r)[55]), \
           "r"((r)[56]), "r"((r)[57]), "r"((r)[58]), "r"((r)[59]), \
           "r"((r)[60]), "r"((r)[61]), "r"((r)[62]), "r"((r)[63]) \
        : "memory")

#define LDTM_X32(r, ta) \
    asm volatile( \
        "tcgen05.ld.sync.aligned.32x32b.x32.b32 " \
        "{%0, %1, %2, %3, %4, %5, %6, %7, %8, %9, %10, %11, %12, %13, %14, %15, " \
        " %16, %17, %18, %19, %20, %21, %22, %23, %24, %25, %26, %27, %28, %29, %30, %31}, [%32];" \
        : "=r"((r)[0]),  "=r"((r)[1]),  "=r"((r)[2]),  "=r"((r)[3]), \
          "=r"((r)[4]),  "=r"((r)[5]),  "=r"((r)[6]),  "=r"((r)[7]), \
          "=r"((r)[8]),  "=r"((r)[9]),  "=r"((r)[10]), "=r"((r)[11]), \
          "=r"((r)[12]), "=r"((r)[13]), "=r"((r)[14]), "=r"((r)[15]), \
          "=r"((r)[16]), "=r"((r)[17]), "=r"((r)[18]), "=r"((r)[19]), \
          "=r"((r)[20]), "=r"((r)[21]), "=r"((r)[22]), "=r"((r)[23]), \
          "=r"((r)[24]), "=r"((r)[25]), "=r"((r)[26]), "=r"((r)[27]), \
          "=r"((r)[28]), "=r"((r)[29]), "=r"((r)[30]), "=r"((r)[31]) \
        : "r"(ta))
#endif

// idesc VERBATIM from verified test_mma_iter: c=F32, a=BF16 K-major, b=BF16 K-major, M=128, N=32
static constexpr uint32_t IDESC_M128N32 = 0x8080490u;

// smem: [0:4) tmem ptr | [16:24) mbar | B tiles at first 1024-boundary >= +64 (4 x 8KB blocked-atom)
static constexpr int SM_TMEM  = 0;
static constexpr int SM_MBAR  = 16;
static constexpr int SMEM_DYN = 1024 + 64 + 4 * 8192 + 64;   // 33920 < 48KB: NO attribute needed

// TMEM columns: Ah @0..63, Al @64..127, D tiles @128+32j (j=0..3)
static constexpr int TM_AH = 0;
static constexpr int TM_AL = 64;
static constexpr int TM_D  = 128;
static constexpr int TMEM_COLS = 256;

// ---------------- zero out + gate sums + flag ----------------
__global__ void zero_kernel(float* out) {
    size_t total4 = (size_t)N_ * C_ / 4;
    size_t stride = (size_t)gridDim.x * blockDim.x;
    for (size_t i = (size_t)blockIdx.x * blockDim.x + threadIdx.x; i < total4; i += stride)
        ((float4*)out)[i] = make_float4(0.f, 0.f, 0.f, 0.f);
    if (blockIdx.x == 0 && threadIdx.x < E_) g_gatesum[threadIdx.x] = 0.0;
    if (blockIdx.x == 0 && threadIdx.x == 0) g_use_simt = 0;
}

// ---------------- split x into bf16 hi/lo ----------------
__global__ void split_x_kernel(const float* __restrict__ x) {
    size_t total2 = (size_t)N_ * C_ / 2;
    size_t stride = (size_t)gridDim.x * blockDim.x;
    for (size_t i = (size_t)blockIdx.x * blockDim.x + threadIdx.x; i < total2; i += stride) {
        float2 v = ((const float2*)x)[i];
        __nv_bfloat162 h, l;
        h.x = __float2bfloat16_rn(v.x);
        l.x = __float2bfloat16_rn(v.x - __bfloat162float(h.x));
        h.y = __float2bfloat16_rn(v.y);
        l.y = __float2bfloat16_rn(v.y - __bfloat162float(h.y));
        ((__nv_bfloat162*)g_x_hi)[i] = h;
        ((__nv_bfloat162*)g_x_lo)[i] = l;
    }
}

// ---------------- transpose + split weights: in [K,Nn] -> out [Nn,K] ----------------
__global__ void tr_split_kernel(const float* __restrict__ w,
                                __nv_bfloat16* __restrict__ oh,
                                __nv_bfloat16* __restrict__ ol,
                                int K, int Nn) {
    int e = blockIdx.z;
    const float* in = w + (size_t)e * K * Nn;
    __nv_bfloat16* outh = oh + (size_t)e * K * Nn;
    __nv_bfloat16* outl = ol + (size_t)e * K * Nn;
    __shared__ float t[32][33];
    int n0 = blockIdx.x * 32, k0 = blockIdx.y * 32;
    int tx = threadIdx.x, ty = threadIdx.y;
    #pragma unroll
    for (int i = 0; i < 4; i++)
        t[ty + 8 * i][tx] = in[(size_t)(k0 + ty + 8 * i) * Nn + n0 + tx];
    __syncthreads();
    #pragma unroll
    for (int i = 0; i < 4; i++) {
        float v = t[tx][ty + 8 * i];
        __nv_bfloat16 h = __float2bfloat16_rn(v);
        __nv_bfloat16 l = __float2bfloat16_rn(v - __bfloat162float(h));
        size_t o = (size_t)(n0 + ty + 8 * i) * K + k0 + tx;
        outh[o] = h;
        outl[o] = l;
    }
}

// ---------------- router (unchanged, verified) ----------------
__global__ void router_kernel(const float* __restrict__ x,
                              const float* __restrict__ noise,
                              const float* __restrict__ w_route,
                              const float* __restrict__ b_route,
                              const float* __restrict__ w_noise,
                              const float* __restrict__ b_noise) {
    int n    = blockIdx.x;
    int tid  = threadIdx.x;
    int lane = tid & 31;
    int wid  = tid >> 5;

    __shared__ float sx[C_];
    __shared__ float s_logit[E_];
    __shared__ float s_v[E_];

    ((float4*)sx)[tid] = ((const float4*)(x + (size_t)n * C_))[tid];
    __syncthreads();

    {
        int e = wid;
        const float* wr = w_route + (size_t)e * C_;
        const float* wn = w_noise + (size_t)e * C_;
        double ar = 0.0, an = 0.0;
        #pragma unroll 8
        for (int i = lane; i < C_; i += 32) {
            double xv = (double)sx[i];
            ar += xv * (double)wr[i];
            an += xv * (double)wn[i];
        }
        #pragma unroll
        for (int d = 16; d > 0; d >>= 1) {
            ar += __shfl_down_sync(0xffffffffu, ar, d);
            an += __shfl_down_sync(0xffffffffu, an, d);
        }
        if (lane == 0) {
            s_logit[e] = (float)ar + b_route[e];
            s_v[e]     = (float)an + b_noise[e];
        }
    }
    __syncthreads();

    if (tid == 0) {
        float noisy[E_];
        #pragma unroll
        for (int e = 0; e < E_; e++) {
            float v  = s_v[e];
            float sp = fmaxf(v, 0.f) + log1pf(expf(-fabsf(v)));
            noisy[e] = s_logit[e] + noise[(size_t)n * E_ + e] * sp;
        }
        int i1 = 0;
        #pragma unroll
        for (int e = 1; e < E_; e++) if (noisy[e] > noisy[i1]) i1 = e;
        int i2 = (i1 == 0) ? 1 : 0;
        #pragma unroll
        for (int e = 0; e < E_; e++) if (e != i1 && noisy[e] > noisy[i2]) i2 = e;

        float e2 = expf(noisy[i2] - noisy[i1]);
        float denom = 1.f + e2;
        float g1 = 1.f / denom;
        float g2 = e2  / denom;

        #pragma unroll
        for (int e = 0; e < E_; e++)
            g_gates[(size_t)n * E_ + e] = (e == i1) ? g1 : ((e == i2) ? g2 : 0.f);
        g_mask[n] = (unsigned char)((1u << i1) | (1u << i2));
        atomicAdd(&g_gatesum[i1], (double)g1);
        atomicAdd(&g_gatesum[i2], (double)g2);
    }
}

// ---------------- per-expert capacity scan (unchanged, verified) ----------------
__global__ void scan_kernel() {
    int e    = blockIdx.x;
    int tid  = threadIdx.x;
    int lane = tid & 31;
    int wid  = tid >> 5;

    __shared__ int wsum[32];
    __shared__ int s_total;

    int offset = 0;
    for (int chunk = 0; chunk < N_ / 1024; chunk++) {
        int n   = chunk * 1024 + tid;
        int bit = (g_mask[n] >> e) & 1;

        unsigned bal = __ballot_sync(0xffffffffu, bit);
        int pre  = __popc(bal & ((1u << lane) - 1u));
        int wtot = __popc(bal);
        if (lane == 0) wsum[wid] = wtot;
        __syncthreads();
        if (tid < 32) {
            int v0 = wsum[tid];
            int v  = v0;
            #pragma unroll
            for (int d = 1; d < 32; d <<= 1) {
                int t = __shfl_up_sync(0xffffffffu, v, d);
                if (tid >= d) v += t;
            }
            if (tid == 31) s_total = v;
            wsum[tid] = v - v0;
        }
        __syncthreads();
        if (bit) {
            int pos = offset + wsum[wid] + pre;
            if (pos < CAP_) {
                g_dispatch[e * CAP_ + pos] = n;
                g_gslot[e * CAP_ + pos]    = g_gates[(size_t)n * E_ + e];
            }
        }
        offset += s_total;
        __syncthreads();
    }
    if (tid == 0) g_count[e] = offset < CAP_ ? offset : CAP_;
}

// ---------------- load-balance loss ----------------
__global__ void loss_kernel(float* out) {
    if (threadIdx.x == 0 && blockIdx.x == 0) {
        double acc = 0.0;
        #pragma unroll
        for (int e = 0; e < E_; e++) {
            double fr = g_gatesum[e] / (double)N_;
            double d  = fr - 1.0 / (double)E_;
            acc += d * d;
        }
        out[(size_t)N_ * C_] = (float)(0.01 * (acc / (double)E_));
    }
}

#if HAS_TC
// ---- stage A chunk row (128 bf16 = 64 b32) from gmem into TMEM via tcgen05.st x64 ----
__device__ __forceinline__ void stage_a_row(uint32_t tmem_col0, uint32_t woff,
                                            const char* src) {
    uint32_t a[64];
    const float4* s = (const float4*)src;
    #pragma unroll
    for (int i = 0; i < 16; i++) {
        float4 v = s[i];
        a[4 * i + 0] = __float_as_uint(v.x);
        a[4 * i + 1] = __float_as_uint(v.y);
        a[4 * i + 2] = __float_as_uint(v.z);
        a[4 * i + 3] = __float_as_uint(v.w);
    }
    TCG_ST_X64(tmem_col0 + woff, a);
}

// ---- stage B chunk (this thread's row) into blocked-atom SW128 smem (layout of test_mma_iter) ----
__device__ __forceinline__ void stage_b_row(char* btile, uint32_t bbase, int r,
                                            const char* src) {
    const float4* s = (const float4*)src;
    #pragma unroll
    for (int i = 0; i < 16; i++) {
        uint32_t boff = (uint32_t)((r >> 3) + (i >> 3) * 4) * 1024u
                      + (uint32_t)(r & 7) * 128u + (uint32_t)(i & 7) * 16u;
        *(float4*)(btile + bbase + swz(boff)) = s[i];
    }
}

// ---- TS mainloop: D(128x128) += A(128xK) @ B(128xK)^T with 3-term bf16 split ----
__device__ __forceinline__ void ts_mainloop(uint32_t sb, char* btile, int tid, int wid, int NC,
                                            uint32_t tmem,
                                            const char* pAh, const char* pAl,
                                            const char* pBh, const char* pBl) {
    uint32_t woff  = ((uint32_t)wid) << 21;
    uint32_t btu   = smem_u32(btile);
    uint32_t bbase = (uint32_t)(tid >> 5) * 8192u;
    int r = tid & 31;
    uint32_t ph = 0;

    for (int c = 0; c < NC; c++) {
        if (c > 0) {                       // wait: previous chunk's 2nd MMA batch done
            mbar_wait(sb + SM_MBAR, ph & 1); ph++;
            TCG_FENCE_AFTER();
        }
        // A chunk -> TMEM (Ah cols 0..63, Al cols 64..127)
        stage_a_row(tmem + TM_AH, woff, pAh + (size_t)c * 256);
        stage_a_row(tmem + TM_AL, woff, pAl + (size_t)c * 256);
        TCG_WAIT_ST();
        // Bh chunk -> smem
        stage_b_row(btile, bbase, r, pBh + (size_t)c * 256);
        TCG_FENCE_BEFORE();
        FENCE_ASYNC();
        __syncthreads();
        if (wid == 0 && elect_one_pred()) {
            TCG_FENCE_AFTER();
            uint64_t dB = make_desc(btu);
            #pragma unroll
            for (int j = 0; j < 4; j++) {
                uint32_t dtm = tmem + TM_D + j * 32;
                #pragma unroll
                for (int k = 0; k < 8; k++) {
                    uint64_t off = dB + (uint64_t)j * 512 + (uint64_t)((k & 3) * 2 + (k >> 2) * 256);
                    uint32_t en0 = (c == 0 && k == 0) ? 0u : 1u;
                    mma_f16_ts(dtm, tmem + TM_AH + k * 8, off, IDESC_M128N32, en0);  // Ah*Bh
                    mma_f16_ts(dtm, tmem + TM_AL + k * 8, off, IDESC_M128N32, 1u);   // Al*Bh
                }
            }
            TCG_COMMIT(sb + SM_MBAR);
        }
        mbar_wait(sb + SM_MBAR, ph & 1); ph++;   // Bh batch done -> safe to overwrite B smem
        TCG_FENCE_AFTER();
        // Bl chunk -> smem (same region)
        stage_b_row(btile, bbase, r, pBl + (size_t)c * 256);
        FENCE_ASYNC();
        __syncthreads();
        if (wid == 0 && elect_one_pred()) {
            uint64_t dB = make_desc(btu);
            #pragma unroll
            for (int j = 0; j < 4; j++) {
                uint32_t dtm = tmem + TM_D + j * 32;
                #pragma unroll
                for (int k = 0; k < 8; k++) {
                    uint64_t off = dB + (uint64_t)j * 512 + (uint64_t)((k & 3) * 2 + (k >> 2) * 256);
                    mma_f16_ts(dtm, tmem + TM_AH + k * 8, off, IDESC_M128N32, 1u);   // Ah*Bl
                }
            }
            TCG_COMMIT(sb + SM_MBAR);
        }
    }
    mbar_wait(sb + SM_MBAR, ph & 1); ph++;
    TCG_FENCE_AFTER();
}
#endif  // HAS_TC

// ---------------- FFN1 (tensor): h = relu(x[dispatch] @ w1 + b1) ----------------
__global__ __launch_bounds__(128)
#if HAS_TC
__cluster_dims__(1, 1, 1)
#endif
void ffn1_tc(const float* __restrict__ b1) {
#if HAS_TC
    int e  = blockIdx.z;
    int bn = blockIdx.x;   // H tile (32)
    int bm = blockIdx.y;   // M tile (32)
    int cnt = g_count[e];
    if (bm * 128 >= cnt) return;

    extern __shared__ char smem[];
    uint32_t sb = smem_u32(smem);
    char* btile = smem + ((((sb + 64u + 1023u) & ~1023u)) - sb);
    int tid = threadIdx.x, wid = tid >> 5;

    if (tid == 0) MBAR_INIT(sb + SM_MBAR, 1);
    if (wid == 0) { TCG_ALLOC(sb + SM_TMEM, TMEM_COLS); TCG_RELINQ(); }
    __syncthreads();
    uint32_t tmem;
    asm volatile("ld.shared.b32 %0, [%1];" : "=r"(tmem) : "r"(sb + SM_TMEM));

    int rowg = bm * 128 + tid;
    bool valid = rowg < cnt;
    int tok = valid ? g_dispatch[e * CAP_ + rowg] : 0;

    const char* pAh = (const char*)(g_x_hi + (size_t)tok * C_);
    const char* pAl = (const char*)(g_x_lo + (size_t)tok * C_);
    const char* pBh = (const char*)(g_w1t_hi + ((size_t)e * H_ + bn * 128 + tid) * C_);
    const char* pBl = (const char*)(g_w1t_lo + ((size_t)e * H_ + bn * 128 + tid) * C_);

    ts_mainloop(sb, btile, tid, wid, C_ / 128, tmem, pAh, pAl, pBh, pBl);

    // epilogue: bias + relu + bf16 hi/lo split -> g_h (row == tid)
    size_t hbase = ((size_t)e * CAP_ + rowg) * H_ + (size_t)bn * 128;
    #pragma unroll
    for (int nb = 0; nb < 4; nb++) {
        uint32_t dr[32];
        LDTM_X32(dr, tmem + TM_D + nb * 32);
        TCG_WAIT_LD();
        if (valid) {
            #pragma unroll
            for (int j = 0; j < 32; j += 2) {
                int col = bn * 128 + nb * 32 + j;
                float v0 = __uint_as_float(dr[j])     + b1[(size_t)e * H_ + col];
                float v1 = __uint_as_float(dr[j + 1]) + b1[(size_t)e * H_ + col + 1];
                v0 = v0 > 0.f ? v0 : 0.f;
                v1 = v1 > 0.f ? v1 : 0.f;
                __nv_bfloat162 hh, ll;
                hh.x = __float2bfloat16_rn(v0);
                ll.x = __float2bfloat16_rn(v0 - __bfloat162float(hh.x));
                hh.y = __float2bfloat16_rn(v1);
                ll.y = __float2bfloat16_rn(v1 - __bfloat162float(hh.y));
                *(__nv_bfloat162*)(g_h_hi + hbase + nb * 32 + j) = hh;
                *(__nv_bfloat162*)(g_h_lo + hbase + nb * 32 + j) = ll;
            }
        }
    }
    TCG_FENCE_BEFORE();
    __syncthreads();
    if (wid == 0) TCG_DEALLOC(tmem, TMEM_COLS);
#endif
}

// ---------------- check: validate ffn1_tc output vs fp32 reference on samples ----------------
__global__ void check_h_kernel(const float* __restrict__ x,
                               const float* __restrict__ w1,
                               const float* __restrict__ b1) {
    int tid  = threadIdx.x;
    int lane = tid & 31;
    int wid  = tid >> 5;
    int wg   = blockIdx.x * (blockDim.x >> 5) + wid;   // global warp id

    #pragma unroll 1
    for (int q = 0; q < 4; q++) {
        int s = wg * 4 + q;                 // sample id 0..127
        int e = s & 7;
        int cnt = g_count[e];
        if (cnt <= 0) continue;
        int row = (s * 37 + 5) % cnt;
        int col = (s * 911 + 13) % H_;
        int tok = g_dispatch[e * CAP_ + row];
        const float* xr = x + (size_t)tok * C_;
        const float* wc = w1 + (size_t)e * C_ * H_ + col;
        float acc = 0.f;
        for (int k = lane; k < C_; k += 32)
            acc += xr[k] * wc[(size_t)k * H_];
        #pragma unroll
        for (int d = 16; d > 0; d >>= 1)
            acc += __shfl_down_sync(0xffffffffu, acc, d);
        if (lane == 0) {
            float ref = acc + b1[(size_t)e * H_ + col];
            ref = ref > 0.f ? ref : 0.f;
            size_t o = ((size_t)e * CAP_ + row) * H_ + col;
            float got = __bfloat162float(g_h_hi[o]) + __bfloat162float(g_h_lo[o]);
            if (fabsf(got - ref) > 0.05f * fmaxf(fabsf(ref), 1.0f))
                g_use_simt = 1;
        }
    }
}

// ---------------- FFN2 (tensor): out[tok] += gate*(h @ w2 + b2) ----------------
__global__ __launch_bounds__(128)
#if HAS_TC
__cluster_dims__(1, 1, 1)
#endif
void ffn2_tc(const float* __restrict__ b2, float* __restrict__ out) {
#if HAS_TC
    if (*(volatile int*)&g_use_simt) return;   // tc FFN1 failed validation -> SIMT path owns output
    int e  = blockIdx.z;
    int bn = blockIdx.x;   // C tile (8)
    int bm = blockIdx.y;   // M tile (32)
    int cnt = g_count[e];
    if (bm * 128 >= cnt) return;

    extern __shared__ char smem[];
    uint32_t sb = smem_u32(smem);
    char* btile = smem + ((((sb + 64u + 1023u) & ~1023u)) - sb);
    int tid = threadIdx.x, wid = tid >> 5;

    if (tid == 0) MBAR_INIT(sb + SM_MBAR, 1);
    if (wid == 0) { TCG_ALLOC(sb + SM_TMEM, TMEM_COLS); TCG_RELINQ(); }
    __syncthreads();
    uint32_t tmem;
    asm volatile("ld.shared.b32 %0, [%1];" : "=r"(tmem) : "r"(sb + SM_TMEM));

    int rowg = bm * 128 + tid;
    bool valid = rowg < cnt;

    const char* pAh = (const char*)(g_h_hi + ((size_t)e * CAP_ + rowg) * H_);
    const char* pAl = (const char*)(g_h_lo + ((size_t)e * CAP_ + rowg) * H_);
    const char* pBh = (const char*)(g_w2t_hi + ((size_t)e * C_ + bn * 128 + tid) * H_);
    const char* pBl = (const char*)(g_w2t_lo + ((size_t)e * C_ + bn * 128 + tid) * H_);

    ts_mainloop(sb, btile, tid, wid, H_ / 128, tmem, pAh, pAl, pBh, pBl);

    // epilogue: bias + gate scale + atomic scatter (row == tid)
    int   tok = 0;
    float g   = 0.f;
    if (valid) {
        tok = g_dispatch[e * CAP_ + rowg];
        g   = g_gslot[e * CAP_ + rowg];
    }
    #pragma unroll
    for (int nb = 0; nb < 4; nb++) {
        uint32_t dr[32];
        LDTM_X32(dr, tmem + TM_D + nb * 32);
        TCG_WAIT_LD();
        if (valid) {
            #pragma unroll
            for (int j = 0; j < 32; j++) {
                int col = bn * 128 + nb * 32 + j;
                float v = (__uint_as_float(dr[j]) + b2[(size_t)e * C_ + col]) * g;
                atomicAdd(out + (size_t)tok * C_ + col, v);
            }
        }
    }
    TCG_FENCE_BEFORE();
    __syncthreads();
    if (wid == 0) TCG_DEALLOC(tmem, TMEM_COLS);
#endif
}

// ---------------- SIMT fallback FFN (compiled always; runs only if g_use_simt) ----------------
static constexpr int BM = 128, BN = 128, BK = 8, TM = 8, TN = 8;

__global__ __launch_bounds__(256, 2)
void ffn1_simt(const float* __restrict__ x,
               const float* __restrict__ w1,
               const float* __restrict__ b1) {
    if (*(volatile int*)&g_use_simt == 0) return;
    int e   = blockIdx.z;
    int cnt = g_count[e];
    int bm  = blockIdx.y, bn = blockIdx.x;
    if (bm * BM >= cnt) return;

    __shared__ float As[BK][BM];
    __shared__ float Bs[BK][BN];
    __shared__ int   stok[BM];

    int tid = threadIdx.x;
    if (tid < BM) {
        int rr = bm * BM + tid;
        stok[tid] = (rr < cnt) ? g_dispatch[e * CAP_ + rr] : -1;
    }
    __syncthreads();

    int arow = tid >> 1, ak = (tid & 1) * 4;
    int brow = tid >> 5, bcol = (tid & 31) * 4;
    int ty = tid >> 4, tx = tid & 15;

    int tok = stok[arow];
    const float* Arow  = x  + (size_t)(tok < 0 ? 0 : tok) * C_;
    const float* Bbase = w1 + (size_t)e * C_ * H_ + (size_t)bn * BN;

    float acc[TM][TN];
    #pragma unroll
    for (int i = 0; i < TM; i++)
        #pragma unroll
        for (int j = 0; j < TN; j++) acc[i][j] = 0.f;

    for (int kk = 0; kk < C_; kk += BK) {
        float4 av = make_float4(0.f, 0.f, 0.f, 0.f);
        if (tok >= 0) av = *(const float4*)(Arow + kk + ak);
        As[ak + 0][arow] = av.x;
        As[ak + 1][arow] = av.y;
        As[ak + 2][arow] = av.z;
        As[ak + 3][arow] = av.w;
        *(float4*)&Bs[brow][bcol] = *(const float4*)(Bbase + (size_t)(kk + brow) * H_ + bcol);
        __syncthreads();
        #pragma unroll
        for (int k = 0; k < BK; k++) {
            float ra[TM], rb[TN];
            *(float4*)&ra[0] = *(const float4*)&As[k][ty * TM];
            *(float4*)&ra[4] = *(const float4*)&As[k][ty * TM + 4];
            *(float4*)&rb[0] = *(const float4*)&Bs[k][tx * TN];
            *(float4*)&rb[4] = *(const float4*)&Bs[k][tx * TN + 4];
            #pragma unroll
            for (int i = 0; i < TM; i++)
                #pragma unroll
                for (int j = 0; j < TN; j++)
                    acc[i][j] = fmaf(ra[i], rb[j], acc[i][j]);
        }
        __syncthreads();
    }

    int row0 = bm * BM + ty * TM;
    int col0 = bn * BN + tx * TN;
    #pragma unroll
    for (int i = 0; i < TM; i++) {
        int row = row0 + i;
        if (row < cnt) {
            float* hp = g_h_f32 + ((size_t)e * CAP_ + row) * H_ + col0;
            #pragma unroll
            for (int j = 0; j < TN; j++) {
                float v = acc[i][j] + b1[(size_t)e * H_ + col0 + j];
                hp[j] = v > 0.f ? v : 0.f;
            }
        }
    }
}

__global__ __launch_bounds__(256, 2)
void ffn2_simt(const float* __restrict__ w2,
               const float* __restrict__ b2,
               float* __restrict__ out) {
    if (*(volatile int*)&g_use_simt == 0) return;
    int e   = blockIdx.z;
    int cnt = g_count[e];
    int bm  = blockIdx.y, bn = blockIdx.x;
    if (bm * BM >= cnt) return;

    __shared__ float As[BK][BM];
    __shared__ float Bs[BK][BN];

    int tid  = threadIdx.x;
    int arow = tid >> 1, ak = (tid & 1) * 4;
    int brow = tid >> 5, bcol = (tid & 31) * 4;
    int ty = tid >> 4, tx = tid & 15;

    int grow = bm * BM + arow;
    bool avalid = grow < cnt;
    const float* Arow  = g_h_f32 + ((size_t)e * CAP_ + (avalid ? grow : 0)) * H_;
    const float* Bbase = w2  + (size_t)e * H_ * C_ + (size_t)bn * BN;

    float acc[TM][TN];
    #pragma unroll
    for (int i = 0; i < TM; i++)
        #pragma unroll
        for (int j = 0; j < TN; j++) acc[i][j] = 0.f;

    for (int kk = 0; kk < H_; kk += BK) {
        float4 av = avalid ? *(const float4*)(Arow + kk + ak)
                           : make_float4(0.f, 0.f, 0.f, 0.f);
        As[ak + 0][arow] = av.x;
        As[ak + 1][arow] = av.y;
        As[ak + 2][arow] = av.z;
        As[ak + 3][arow] = av.w;
        *(float4*)&Bs[brow][bcol] = *(const float4*)(Bbase + (size_t)(kk + brow) * C_ + bcol);
        __syncthreads();
        #pragma unroll
        for (int k = 0; k < BK; k++) {
            float ra[TM], rb[TN];
            *(float4*)&ra[0] = *(const float4*)&As[k][ty * TM];
            *(float4*)&ra[4] = *(const float4*)&As[k][ty * TM + 4];
            *(float4*)&rb[0] = *(const float4*)&Bs[k][tx * TN];
            *(float4*)&rb[4] = *(const float4*)&Bs[k][tx * TN + 4];
            #pragma unroll
            for (int i = 0; i < TM; i++)
                #pragma unroll
                for (int j = 0; j < TN; j++)
                    acc[i][j] = fmaf(ra[i], rb[j], acc[i][j]);
        }
        __syncthreads();
    }

    int row0 = bm * BM + ty * TM;
    int col0 = bn * BN + tx * TN;
    #pragma unroll
    for (int i = 0; i < TM; i++) {
        int row = row0 + i;
        if (row < cnt) {
            int   tok = g_dispatch[e * CAP_ + row];
            float g   = g_gslot[e * CAP_ + row];
            float* op = out + (size_t)tok * C_ + col0;
            #pragma unroll
            for (int j = 0; j < TN; j++) {
                float v = (acc[i][j] + b2[(size_t)e * C_ + col0 + j]) * g;
                atomicAdd(&op[j], v);
            }
        }
    }
}

// ---------------- launch ----------------
extern "C" void kernel_launch(void* const* d_in, const int* in_sizes, int n_in,
                              void* d_out, int out_size) {
    const float* x       = (const float*)d_in[0];
    const float* noise   = (const float*)d_in[1];
    const float* w_route = (const float*)d_in[2];
    const float* b_route = (const float*)d_in[3];
    const float* w_noise = (const float*)d_in[4];
    const float* b_noise = (const float*)d_in[5];
    const float* w1      = (const float*)d_in[6];
    const float* b1      = (const float*)d_in[7];
    const float* w2      = (const float*)d_in[8];
    const float* b2      = (const float*)d_in[9];
    float* out = (float*)d_out;

    zero_kernel<<<2048, 256>>>(out);
    split_x_kernel<<<4096, 256>>>(x);
    tr_split_kernel<<<dim3(H_ / 32, C_ / 32, E_), dim3(32, 8)>>>(w1, g_w1t_hi, g_w1t_lo, C_, H_);
    tr_split_kernel<<<dim3(C_ / 32, H_ / 32, E_), dim3(32, 8)>>>(w2, g_w2t_hi, g_w2t_lo, H_, C_);
    router_kernel<<<N_, 256>>>(x, noise, w_route, b_route, w_noise, b_noise);
    scan_kernel<<<E_, 1024>>>();
    loss_kernel<<<1, 32>>>(out);

    // tensor FFN1 (real body only in sm_103a image; empty elsewhere)
    ffn1_tc<<<dim3(H_ / 128, CAP_ / 128, E_), 128, SMEM_DYN>>>(b1);
    // validate tc h against fp32 reference samples; sets g_use_simt on mismatch
    check_h_kernel<<<4, 256>>>(x, w1, b1);
    // SIMT fallback FFN1 (runs only if validation failed)
    ffn1_simt<<<dim3(H_ / BN, CAP_ / BM, E_), 256>>>(x, w1, b1);
    // tensor FFN2 (skips itself if validation failed)
    ffn2_tc<<<dim3(C_ / 128, CAP_ / 128, E_), 128, SMEM_DYN>>>(b2, out);
    // SIMT fallback FFN2
    ffn2_simt<<<dim3(C_ / BN, CAP_ / BM, E_), 256>>>(w2, b2, out);
}